// round 10
// baseline (speedup 1.0000x reference)
#include <cuda_runtime.h>
#include <math.h>

#define DEG2RAD 0.017453292519943295f
#define CLIP1(v) fminf(fmaxf((v), -1.0f + 1e-5f), 1.0f - 1e-5f)
#define FPB 32   // faces per tile

__device__ __forceinline__ float4 ld4(const float* p) {
    return *reinterpret_cast<const float4*>(p);
}
__device__ __forceinline__ void fma4(float4& r, float v, const float4& w) {
    r.x = fmaf(v, w.x, r.x);
    r.y = fmaf(v, w.y, r.y);
    r.z = fmaf(v, w.z, r.z);
    r.w = fmaf(v, w.w, r.w);
}
__device__ __forceinline__ void st4s(float* p, const float4& r) {
    __stcs(reinterpret_cast<float4*>(p), r);   // streaming (evict-first) store
}

// phase 1: compute the 17 per-face features for face (tile, e) into fr[0..16]
__device__ __forceinline__ void phase1_face(
    const float* __restrict__ vertices, const int* __restrict__ faces,
    const float* __restrict__ theta, const float* __restrict__ phi,
    int V, int F, int tilesPerBatch, int tile, int e, float* fr)
{
    const int bi    = tile / tilesPerBatch;
    const int face0 = (tile - bi * tilesPerBatch) * FPB;
    const int f     = face0 + e;
    if (f >= F) return;

    // normalized incidence direction for this face's batch
    const float th = theta[bi] * DEG2RAD;
    const float ph = phi[bi]   * DEG2RAD;
    float sph, cph, sth, cth;
    sincosf(ph, &sph, &cph);
    sincosf(th, &sth, &cth);
    float ix = sph * cth, iy = sph * sth, iz = cph;
    const float ii = 1.0f / fmaxf(sqrtf(ix*ix + iy*iy + iz*iz), 1e-12f);
    ix *= ii; iy *= ii; iz *= ii;

    const int* fp = faces + ((long long)bi * F + f) * 3;
    const int i0 = fp[0], i1 = fp[1], i2 = fp[2];
    const float* vb = vertices + (long long)bi * V * 3;
    const float Ax = vb[3*i0], Ay = vb[3*i0+1], Az = vb[3*i0+2];
    const float Bx = vb[3*i1], By = vb[3*i1+1], Bz = vb[3*i1+2];
    const float Cx = vb[3*i2], Cy = vb[3*i2+1], Cz = vb[3*i2+2];

    const float e0x = Ax-Cx, e0y = Ay-Cy, e0z = Az-Cz;
    const float e1x = Bx-Ax, e1y = By-Ay, e1z = Bz-Az;
    const float e2x = Cx-Bx, e2y = Cy-By, e2z = Cz-Bz;

    const float r0 = 1.0f / fmaxf(sqrtf(e0x*e0x + e0y*e0y + e0z*e0z), 1e-12f);
    const float r1 = 1.0f / fmaxf(sqrtf(e1x*e1x + e1y*e1y + e1z*e1z), 1e-12f);
    const float r2 = 1.0f / fmaxf(sqrtf(e2x*e2x + e2y*e2y + e2z*e2z), 1e-12f);
    const float n0x = e0x*r0, n0y = e0y*r0, n0z = e0z*r0;
    const float n1x = e1x*r1, n1y = e1y*r1, n1z = e1z*r1;
    const float n2x = e2x*r2, n2y = e2y*r2, n2z = e2z*r2;

    const float nd0 = -(n0x*n0z + n1x*n1z + n2x*n2z);
    const float nd1 = -(n0y*n0x + n1y*n1x + n2y*n2x);
    const float nd2 = -(n0z*n0y + n1z*n1y + n2z*n2y);
    const float a0 = acosf(CLIP1(nd0));
    const float a1 = acosf(CLIP1(nd1));
    const float a2 = acosf(CLIP1(nd2));

    const float crx = e0y*e1z - e0z*e1y;
    const float cry = e0z*e1x - e0x*e1z;
    const float crz = e0x*e1y - e0y*e1x;
    const float cn = sqrtf(crx*crx + cry*cry + crz*crz);
    const float ci = 1.0f / fmaxf(cn, 1e-12f);
    const float nx = crx*ci, ny = cry*ci, nz = crz*ci;
    const float area = 0.5f * cn;
    const float emno = acosf(CLIP1(-(nx*ix + ny*iy + nz*iz)));

    fr[0] = Ax; fr[1] = Ay; fr[2] = Az;
    fr[3] = Bx; fr[4] = By; fr[5] = Bz;
    fr[6] = Cx; fr[7] = Cy; fr[8] = Cz;
    fr[9] = a0; fr[10] = a1; fr[11] = a2;
    fr[12] = nx; fr[13] = ny; fr[14] = nz;
    fr[15] = area; fr[16] = emno;
}

// Output row (1056 floats):
// [0,576)=coor dot9 | [576,624)=angle dot3 | [624,816)=normal dot3 | [816,832)=area dot1
// [832,1024)=emangle CONST | [1024,1040)=emnoangle dot1 | [1040,1056)=emfreq CONST
// Persistent CTAs: each strides over tiles; warp 7 (lightest phase-2 segment)
// computes phase 1 for tile i+1 while warps 0-6 store tile i. One barrier/tile.

__global__ __launch_bounds__(256, 4) void meshcodec_kernel(
    const float* __restrict__ vertices, const int* __restrict__ faces,
    const float* __restrict__ theta, const float* __restrict__ phi,
    const float* __restrict__ freq,
    const float* __restrict__ W_angle,     const float* __restrict__ b_angle,
    const float* __restrict__ W_area,      const float* __restrict__ b_area,
    const float* __restrict__ W_normal,    const float* __restrict__ b_normal,
    const float* __restrict__ W_emnoangle, const float* __restrict__ b_emnoangle,
    const float* __restrict__ W_emangle,   const float* __restrict__ b_emangle,
    const float* __restrict__ W_emfreq,    const float* __restrict__ b_emfreq,
    const float* __restrict__ W_coor,      const float* __restrict__ b_coor,
    float* __restrict__ out, int V, int F, int B)
{
    __shared__ float feat[2][FPB][20];

    const int t  = threadIdx.x;
    const int c0 = t * 4;
    const int tilesPerBatch = (F + FPB - 1) / FPB;
    const int ntiles = B * tilesPerBatch;
    const int stride = gridDim.x;

    // ---- persistent per-thread weight columns ----
    float4 w0, w1, w2, w3, w4, w5, w6, w7, w8;   // seg0 uses all; others use a few
    float4 bb;                                    // bias (or precombined base)
    float4 w2nd, bb2, wf2;                        // warp-7 extra columns
    bool   dyn2 = false, has2 = false;

    if (c0 < 576) {                               // e_coor
        w0 = ld4(W_coor + 0*576 + c0); w1 = ld4(W_coor + 1*576 + c0);
        w2 = ld4(W_coor + 2*576 + c0); w3 = ld4(W_coor + 3*576 + c0);
        w4 = ld4(W_coor + 4*576 + c0); w5 = ld4(W_coor + 5*576 + c0);
        w6 = ld4(W_coor + 6*576 + c0); w7 = ld4(W_coor + 7*576 + c0);
        w8 = ld4(W_coor + 8*576 + c0);
        bb = ld4(b_coor + c0);
    } else if (c0 < 624) {                        // e_angle
        const int l = c0 - 576;
        w0 = ld4(W_angle + l); w1 = ld4(W_angle + 48 + l); w2 = ld4(W_angle + 96 + l);
        bb = ld4(b_angle + l);
    } else if (c0 < 816) {                        // e_normal
        const int l = c0 - 624;
        w0 = ld4(W_normal + l); w1 = ld4(W_normal + 192 + l); w2 = ld4(W_normal + 384 + l);
        bb = ld4(b_normal + l);
    } else if (c0 < 832) {                        // e_area
        const int l = c0 - 816;
        w0 = ld4(W_area + l);
        bb = ld4(b_area + l);
    } else {                                      // e_emangle (const per batch)
        const int l = c0 - 832;
        w0 = ld4(W_emangle + l);
        w1 = ld4(W_emangle + 192 + l);
        w2 = ld4(W_emangle + 384 + l);
        bb = ld4(b_emangle + l);
        const int e = t - 224;                    // warp-7 extra cols [1024,1056)
        if (e >= 0 && e < 8) {
            has2 = true;
            if (e < 4) {
                w2nd = ld4(W_emnoangle + 4 * e);
                bb2  = ld4(b_emnoangle + 4 * e);
                dyn2 = true;
            } else {
                const int l2 = 4 * (e - 4);
                wf2 = ld4(W_emfreq + l2);
                bb2 = ld4(b_emfreq + l2);
            }
        }
    }

    // ---- prologue: phase 1 for first tile ----
    if (t >= 224 && blockIdx.x < ntiles)
        phase1_face(vertices, faces, theta, phi, V, F, tilesPerBatch,
                    blockIdx.x, t - 224, feat[0][t - 224]);
    __syncthreads();

    int buf = 0;
    for (int tile = blockIdx.x; tile < ntiles; tile += stride) {
        // phase 1 for next tile (warp 7) — overlaps with phase 2 below
        const int nxt = tile + stride;
        if (t >= 224 && nxt < ntiles)
            phase1_face(vertices, faces, theta, phi, V, F, tilesPerBatch,
                        nxt, t - 224, feat[buf ^ 1][t - 224]);

        // ---- phase 2 for current tile ----
        const int bi    = tile / tilesPerBatch;
        const int face0 = (tile - bi * tilesPerBatch) * FPB;
        const int nf    = min(FPB, F - face0);
        const long long fb = (long long)bi * F + face0;
        float* op = out + fb * 1056 + c0;
        float (*ft)[20] = feat[buf];

        if (c0 < 576) {                           // dot9
            #pragma unroll 2
            for (int f = 0; f < nf; f++, op += 1056) {
                const float* ftp = ft[f];
                const float4 p0 = *reinterpret_cast<const float4*>(ftp);
                const float4 p1 = *reinterpret_cast<const float4*>(ftp + 4);
                const float p8 = ftp[8];
                float4 r = bb;
                fma4(r, p0.x, w0); fma4(r, p0.y, w1); fma4(r, p0.z, w2);
                fma4(r, p0.w, w3); fma4(r, p1.x, w4); fma4(r, p1.y, w5);
                fma4(r, p1.z, w6); fma4(r, p1.w, w7); fma4(r, p8,   w8);
                st4s(op, r);
            }
        } else if (c0 < 624) {                    // angle dot3
            #pragma unroll 4
            for (int f = 0; f < nf; f++, op += 1056) {
                const float* ftp = ft[f];
                float4 r = bb;
                fma4(r, ftp[9], w0); fma4(r, ftp[10], w1); fma4(r, ftp[11], w2);
                st4s(op, r);
            }
        } else if (c0 < 816) {                    // normal dot3
            #pragma unroll 4
            for (int f = 0; f < nf; f++, op += 1056) {
                const float* ftp = ft[f];
                float4 r = bb;
                fma4(r, ftp[12], w0); fma4(r, ftp[13], w1); fma4(r, ftp[14], w2);
                st4s(op, r);
            }
        } else if (c0 < 832) {                    // area dot1
            #pragma unroll 4
            for (int f = 0; f < nf; f++, op += 1056) {
                float4 r = bb;
                fma4(r, ft[f][15], w0);
                st4s(op, r);
            }
        } else {                                  // emangle const + extra cols
            const float th = theta[bi] * DEG2RAD;
            const float ph = phi[bi]   * DEG2RAD;
            float sph, cph, sth, cth;
            sincosf(ph, &sph, &cph);
            sincosf(th, &sth, &cth);
            const float incx = sph * cth, incy = sph * sth, incz = cph;
            float4 base = bb;
            base.x += incx*w0.x + incy*w1.x + incz*w2.x;
            base.y += incx*w0.y + incy*w1.y + incz*w2.y;
            base.z += incx*w0.z + incy*w1.z + incz*w2.z;
            base.w += incx*w0.w + incy*w1.w + incz*w2.w;

            float4 base2 = bb2;
            if (has2 && !dyn2) {
                const float freq_log = (log10f(freq[bi]) + 1.0f) * 0.5f;
                base2.x = fmaf(freq_log, wf2.x, bb2.x);
                base2.y = fmaf(freq_log, wf2.y, bb2.y);
                base2.z = fmaf(freq_log, wf2.z, bb2.z);
                base2.w = fmaf(freq_log, wf2.w, bb2.w);
            }
            float* op2 = out + fb * 1056 + 1024 + 4 * (t - 224);
            #pragma unroll 4
            for (int f = 0; f < nf; f++, op += 1056, op2 += 1056) {
                st4s(op, base);
                if (has2) {
                    float4 r2 = base2;
                    if (dyn2) fma4(r2, ft[f][16], w2nd);
                    st4s(op2, r2);
                }
            }
        }

        __syncthreads();
        buf ^= 1;
    }
}

extern "C" void kernel_launch(void* const* d_in, const int* in_sizes, int n_in,
                              void* d_out, int out_size) {
    const float* vertices     = (const float*)d_in[0];
    const int*   faces        = (const int*)  d_in[1];
    const float* theta        = (const float*)d_in[2];
    const float* phi          = (const float*)d_in[3];
    const float* freq         = (const float*)d_in[4];
    const float* W_angle      = (const float*)d_in[5];
    const float* b_angle      = (const float*)d_in[6];
    const float* W_area       = (const float*)d_in[7];
    const float* b_area       = (const float*)d_in[8];
    const float* W_normal     = (const float*)d_in[9];
    const float* b_normal     = (const float*)d_in[10];
    const float* W_emnoangle  = (const float*)d_in[11];
    const float* b_emnoangle  = (const float*)d_in[12];
    const float* W_emangle    = (const float*)d_in[13];
    const float* b_emangle    = (const float*)d_in[14];
    const float* W_emfreq     = (const float*)d_in[15];
    const float* b_emfreq     = (const float*)d_in[16];
    const float* W_coor       = (const float*)d_in[17];
    const float* b_coor       = (const float*)d_in[18];
    float* out = (float*)d_out;

    const int B = in_sizes[2];
    const int F = in_sizes[1] / (3 * B);
    const int V = in_sizes[0] / (3 * B);

    const int ntiles = B * ((F + FPB - 1) / FPB);
    int grid = 148 * 4;                 // persistent: exactly 4 CTAs per SM
    if (grid > ntiles) grid = ntiles;

    meshcodec_kernel<<<grid, 256>>>(
        vertices, faces, theta, phi, freq,
        W_angle, b_angle, W_area, b_area, W_normal, b_normal,
        W_emnoangle, b_emnoangle, W_emangle, b_emangle,
        W_emfreq, b_emfreq, W_coor, b_coor,
        out, V, F, B);
}

// round 13
// speedup vs baseline: 1.0413x; 1.0413x over previous
#include <cuda_runtime.h>
#include <math.h>

#define DEG2RAD 0.017453292519943295f
#define CLIP1(v) fminf(fmaxf((v), -1.0f + 1e-5f), 1.0f - 1e-5f)
#define FPB 32          // faces per block in phase-2
#define MAXFACES 163840 // >= B*F = 8*20000

// SoA-of-float4 feature scratch (static __device__, no allocation):
// f0 = (Ax,Ay,Az,Bx)  f1 = (By,Bz,Cx,Cy)  f2 = (Cz,a0,a1,a2)  f3 = (nx,ny,nz,area)
__device__ float4 g_f0[MAXFACES];
__device__ float4 g_f1[MAXFACES];
__device__ float4 g_f2[MAXFACES];
__device__ float4 g_f3[MAXFACES];
__device__ float  g_femno[MAXFACES];

__device__ __forceinline__ float4 ld4(const float* p) {
    return *reinterpret_cast<const float4*>(p);
}
__device__ __forceinline__ void fma4(float4& r, float v, const float4& w) {
    r.x = fmaf(v, w.x, r.x);
    r.y = fmaf(v, w.y, r.y);
    r.z = fmaf(v, w.z, r.z);
    r.w = fmaf(v, w.w, r.w);
}
__device__ __forceinline__ void st4s(float* p, const float4& r) {
    __stcs(reinterpret_cast<float4*>(p), r);   // streaming (evict-first) store
}

// ---------------- K1: per-face features, one thread per face ----------------
__global__ __launch_bounds__(256) void phase1_kernel(
    const float* __restrict__ vertices, const int* __restrict__ faces,
    const float* __restrict__ theta, const float* __restrict__ phi,
    int V, int F, int total)
{
    const int g = blockIdx.x * blockDim.x + threadIdx.x;
    if (g >= total) return;
    const int bi = g / F;

    const int* fp = faces + (long long)g * 3;
    const int i0 = fp[0], i1 = fp[1], i2 = fp[2];
    const float* vb = vertices + (long long)bi * V * 3;
    const float Ax = vb[3*i0], Ay = vb[3*i0+1], Az = vb[3*i0+2];
    const float Bx = vb[3*i1], By = vb[3*i1+1], Bz = vb[3*i1+2];
    const float Cx = vb[3*i2], Cy = vb[3*i2+1], Cz = vb[3*i2+2];

    const float e0x = Ax-Cx, e0y = Ay-Cy, e0z = Az-Cz;
    const float e1x = Bx-Ax, e1y = By-Ay, e1z = Bz-Az;
    const float e2x = Cx-Bx, e2y = Cy-By, e2z = Cz-Bz;

    const float r0 = 1.0f / fmaxf(sqrtf(e0x*e0x + e0y*e0y + e0z*e0z), 1e-12f);
    const float r1 = 1.0f / fmaxf(sqrtf(e1x*e1x + e1y*e1y + e1z*e1z), 1e-12f);
    const float r2 = 1.0f / fmaxf(sqrtf(e2x*e2x + e2y*e2y + e2z*e2z), 1e-12f);
    const float n0x = e0x*r0, n0y = e0y*r0, n0z = e0z*r0;
    const float n1x = e1x*r1, n1y = e1y*r1, n1z = e1z*r1;
    const float n2x = e2x*r2, n2y = e2y*r2, n2z = e2z*r2;

    const float nd0 = -(n0x*n0z + n1x*n1z + n2x*n2z);
    const float nd1 = -(n0y*n0x + n1y*n1x + n2y*n2x);
    const float nd2 = -(n0z*n0y + n1z*n1y + n2z*n2y);
    const float a0 = acosf(CLIP1(nd0));
    const float a1 = acosf(CLIP1(nd1));
    const float a2 = acosf(CLIP1(nd2));

    const float crx = e0y*e1z - e0z*e1y;
    const float cry = e0z*e1x - e0x*e1z;
    const float crz = e0x*e1y - e0y*e1x;
    const float cn = sqrtf(crx*crx + cry*cry + crz*crz);
    const float ci = 1.0f / fmaxf(cn, 1e-12f);
    const float nx = crx*ci, ny = cry*ci, nz = crz*ci;
    const float area = 0.5f * cn;

    // normalized incidence direction for this batch
    const float th = theta[bi] * DEG2RAD;
    const float ph = phi[bi]   * DEG2RAD;
    float sph, cph, sth, cth;
    sincosf(ph, &sph, &cph);
    sincosf(th, &sth, &cth);
    float ix = sph * cth, iy = sph * sth, iz = cph;
    const float ii = 1.0f / fmaxf(sqrtf(ix*ix + iy*iy + iz*iz), 1e-12f);
    ix *= ii; iy *= ii; iz *= ii;
    const float emno = acosf(CLIP1(-(nx*ix + ny*iy + nz*iz)));

    g_f0[g] = make_float4(Ax, Ay, Az, Bx);
    g_f1[g] = make_float4(By, Bz, Cx, Cy);
    g_f2[g] = make_float4(Cz, a0, a1, a2);
    g_f3[g] = make_float4(nx, ny, nz, area);
    g_femno[g] = emno;
}

// ---------------- K2: barrier-free streaming phase 2 ----------------
// Output row (1056 floats):
// [0,576)=coor dot9 | [576,624)=angle dot3 | [624,816)=normal dot3 | [816,832)=area dot1
// [832,1024)=emangle CONST | [1024,1040)=emnoangle dot1 | [1040,1056)=emfreq CONST
// Threads 0..255 own cols 4t. Warp-7 threads 224..231 also own cols 1024..1055.
__global__ __launch_bounds__(256, 4) void phase2_kernel(
    const float* __restrict__ theta, const float* __restrict__ phi,
    const float* __restrict__ freq,
    const float* __restrict__ W_angle,     const float* __restrict__ b_angle,
    const float* __restrict__ W_area,      const float* __restrict__ b_area,
    const float* __restrict__ W_normal,    const float* __restrict__ b_normal,
    const float* __restrict__ W_emnoangle, const float* __restrict__ b_emnoangle,
    const float* __restrict__ W_emangle,   const float* __restrict__ b_emangle,
    const float* __restrict__ W_emfreq,    const float* __restrict__ b_emfreq,
    const float* __restrict__ W_coor,      const float* __restrict__ b_coor,
    float* __restrict__ out, int F)
{
    const int t     = threadIdx.x;
    const int bi    = blockIdx.y;
    const int face0 = blockIdx.x * FPB;
    const int c0    = t * 4;
    const int nf    = min(FPB, F - face0);
    const long long gbase = (long long)bi * F + face0;
    float* op = out + gbase * 1056 + c0;

    if (c0 < 576) {                                   // ---- e_coor: dot9 ----
        float4 w0 = ld4(W_coor + 0*576 + c0), w1 = ld4(W_coor + 1*576 + c0);
        float4 w2 = ld4(W_coor + 2*576 + c0), w3 = ld4(W_coor + 3*576 + c0);
        float4 w4 = ld4(W_coor + 4*576 + c0), w5 = ld4(W_coor + 5*576 + c0);
        float4 w6 = ld4(W_coor + 6*576 + c0), w7 = ld4(W_coor + 7*576 + c0);
        float4 w8 = ld4(W_coor + 8*576 + c0);
        const float4 base = ld4(b_coor + c0);
        #pragma unroll 2
        for (int f = 0; f < nf; f++, op += 1056) {
            const float4 p0 = g_f0[gbase + f];
            const float4 p1 = g_f1[gbase + f];
            const float p8 = g_f2[gbase + f].x;
            float4 r = base;
            fma4(r, p0.x, w0); fma4(r, p0.y, w1); fma4(r, p0.z, w2);
            fma4(r, p0.w, w3); fma4(r, p1.x, w4); fma4(r, p1.y, w5);
            fma4(r, p1.z, w6); fma4(r, p1.w, w7); fma4(r, p8,   w8);
            st4s(op, r);
        }
    } else if (c0 < 624) {                            // ---- e_angle: dot3 ----
        const int l = c0 - 576;
        float4 w0 = ld4(W_angle + l), w1 = ld4(W_angle + 48 + l), w2 = ld4(W_angle + 96 + l);
        const float4 base = ld4(b_angle + l);
        #pragma unroll 4
        for (int f = 0; f < nf; f++, op += 1056) {
            const float4 p = g_f2[gbase + f];          // (Cz,a0,a1,a2)
            float4 r = base;
            fma4(r, p.y, w0); fma4(r, p.z, w1); fma4(r, p.w, w2);
            st4s(op, r);
        }
    } else if (c0 < 816) {                            // ---- e_normal: dot3 ----
        const int l = c0 - 624;
        float4 w0 = ld4(W_normal + l), w1 = ld4(W_normal + 192 + l), w2 = ld4(W_normal + 384 + l);
        const float4 base = ld4(b_normal + l);
        #pragma unroll 4
        for (int f = 0; f < nf; f++, op += 1056) {
            const float4 p = g_f3[gbase + f];          // (nx,ny,nz,area)
            float4 r = base;
            fma4(r, p.x, w0); fma4(r, p.y, w1); fma4(r, p.z, w2);
            st4s(op, r);
        }
    } else if (c0 < 832) {                            // ---- e_area: dot1 ----
        const int l = c0 - 816;
        float4 w0 = ld4(W_area + l);
        const float4 base = ld4(b_area + l);
        #pragma unroll 4
        for (int f = 0; f < nf; f++, op += 1056) {
            float4 r = base;
            fma4(r, g_f3[gbase + f].w, w0);
            st4s(op, r);
        }
    } else {                                          // ---- e_emangle CONST + extra cols ----
        const int l = c0 - 832;
        const float4 w0 = ld4(W_emangle + l);
        const float4 w1 = ld4(W_emangle + 192 + l);
        const float4 w2 = ld4(W_emangle + 384 + l);
        const float th = theta[bi] * DEG2RAD;
        const float ph = phi[bi]   * DEG2RAD;
        float sph, cph, sth, cth;
        sincosf(ph, &sph, &cph);
        sincosf(th, &sth, &cth);
        const float incx = sph * cth, incy = sph * sth, incz = cph;
        float4 base = ld4(b_emangle + l);
        base.x += incx*w0.x + incy*w1.x + incz*w2.x;
        base.y += incx*w0.y + incy*w1.y + incz*w2.y;
        base.z += incx*w0.z + incy*w1.z + incz*w2.z;
        base.w += incx*w0.w + incy*w1.w + incz*w2.w;

        const int e = t - 224;                        // warp-7 extra cols [1024,1056)
        const bool has2 = (e >= 0 && e < 8);
        float4 w2nd = make_float4(0.f, 0.f, 0.f, 0.f);
        float4 base2 = make_float4(0.f, 0.f, 0.f, 0.f);
        bool dyn2 = false;
        float* op2 = out + gbase * 1056 + 1024 + 4 * e;
        if (has2) {
            if (e < 4) {                              // e_emnoangle
                w2nd  = ld4(W_emnoangle + 4 * e);
                base2 = ld4(b_emnoangle + 4 * e);
                dyn2 = true;
            } else {                                  // e_emfreq: const
                const int l2 = 4 * (e - 4);
                const float4 wf = ld4(W_emfreq + l2);
                const float freq_log = (log10f(freq[bi]) + 1.0f) * 0.5f;
                base2 = ld4(b_emfreq + l2);
                base2.x = fmaf(freq_log, wf.x, base2.x);
                base2.y = fmaf(freq_log, wf.y, base2.y);
                base2.z = fmaf(freq_log, wf.z, base2.z);
                base2.w = fmaf(freq_log, wf.w, base2.w);
            }
        }
        #pragma unroll 4
        for (int f = 0; f < nf; f++, op += 1056, op2 += 1056) {
            st4s(op, base);
            if (has2) {
                float4 r2 = base2;
                if (dyn2) fma4(r2, g_femno[gbase + f], w2nd);
                st4s(op2, r2);
            }
        }
    }
}

extern "C" void kernel_launch(void* const* d_in, const int* in_sizes, int n_in,
                              void* d_out, int out_size) {
    const float* vertices     = (const float*)d_in[0];
    const int*   faces        = (const int*)  d_in[1];
    const float* theta        = (const float*)d_in[2];
    const float* phi          = (const float*)d_in[3];
    const float* freq         = (const float*)d_in[4];
    const float* W_angle      = (const float*)d_in[5];
    const float* b_angle      = (const float*)d_in[6];
    const float* W_area       = (const float*)d_in[7];
    const float* b_area       = (const float*)d_in[8];
    const float* W_normal     = (const float*)d_in[9];
    const float* b_normal     = (const float*)d_in[10];
    const float* W_emnoangle  = (const float*)d_in[11];
    const float* b_emnoangle  = (const float*)d_in[12];
    const float* W_emangle    = (const float*)d_in[13];
    const float* b_emangle    = (const float*)d_in[14];
    const float* W_emfreq     = (const float*)d_in[15];
    const float* b_emfreq     = (const float*)d_in[16];
    const float* W_coor       = (const float*)d_in[17];
    const float* b_coor       = (const float*)d_in[18];
    float* out = (float*)d_out;

    const int B = in_sizes[2];
    const int F = in_sizes[1] / (3 * B);
    const int V = in_sizes[0] / (3 * B);
    const int total = B * F;

    phase1_kernel<<<(total + 255) / 256, 256>>>(vertices, faces, theta, phi, V, F, total);

    dim3 grid((F + FPB - 1) / FPB, B);
    phase2_kernel<<<grid, 256>>>(
        theta, phi, freq,
        W_angle, b_angle, W_area, b_area, W_normal, b_normal,
        W_emnoangle, b_emnoangle, W_emangle, b_emangle,
        W_emfreq, b_emfreq, W_coor, b_coor,
        out, F);
}